// round 15
// baseline (speedup 1.0000x reference)
#include <cuda_runtime.h>

#define BATCH 2048
#define TT    2048
#define HH    25

typedef unsigned long long u64;

// Packed f32x2 ops (Blackwell, PTX-only): two fp32 ops per instruction.
__device__ __forceinline__ u64 ffma2(u64 a, u64 b, u64 c) {
    u64 d; asm("fma.rn.f32x2 %0, %1, %2, %3;" : "=l"(d) : "l"(a), "l"(b), "l"(c)); return d;
}
__device__ __forceinline__ u64 fmul2(u64 a, u64 b) {
    u64 d; asm("mul.rn.f32x2 %0, %1, %2;" : "=l"(d) : "l"(a), "l"(b)); return d;
}
__device__ __forceinline__ u64 fadd2(u64 a, u64 b) {
    u64 d; asm("add.rn.f32x2 %0, %1, %2;" : "=l"(d) : "l"(a), "l"(b)); return d;
}
__device__ __forceinline__ u64 pk2(float lo, float hi) {
    u64 r; asm("mov.b64 %0, {%1, %2};" : "=l"(r) : "f"(lo), "f"(hi)); return r;
}
__device__ __forceinline__ float lo2(u64 a) { return __uint_as_float((unsigned)a); }
__device__ __forceinline__ float hi2(u64 a) { return __uint_as_float((unsigned)(a >> 32)); }

// MUFU.TANH: single-instruction tanh.
__device__ __forceinline__ float tanha(float x) {
    float r; asm("tanh.approx.f32 %0, %1;" : "=f"(r) : "f"(x)); return r;
}

__device__ __forceinline__ u64 lds64(unsigned a) {
    u64 r; asm volatile("ld.shared.b64 %0, [%1];" : "=l"(r) : "r"(a) : "memory"); return r;
}
__device__ __forceinline__ void lds128(unsigned a, u64& p0, u64& p1) {
    asm volatile("ld.shared.v2.u64 {%0, %1}, [%2];" : "=l"(p0), "=l"(p1) : "r"(a) : "memory");
}
__device__ __forceinline__ void sts32(unsigned a, float v) {
    asm volatile("st.shared.f32 [%0], %1;" :: "r"(a), "f"(v) : "memory");
}

// Unit-owned dual-sequence LSTM, MUFU.TANH, split dot chains, ONE smem
// round-trip per step. Lane j owns unit j of both sequences: all 4 gate dots,
// c_j, h_j are lane-local (no gate exchange). The dense head is a 5th
// lane-uniform dot (every lane computes the same y; lane 0 stores) -- no
// reduction. sigmoid(z) = 0.5 + 0.5*tanh(z/2): i,f,o rows prescaled by 0.5
// (weights+bias+u), g row by 1.0 -> every activation is 1 MUFU (+1 FMA).
// Each 13-pair dot is split into halves (pairs 0-6 / 7-12) merged with one
// packed add: dot-chain latency 28+8 vs 52. Bias rides in pair-12's hi slot
// against the const-1.0 kept in h slot 25. Per step/seq: 6 LDS.128 + 1
// LDS.64, 10 packed-chain dots, tanh ops, ONE STS.32 (h). Warp-private smem,
// in-order per-warp LSU -> no syncwarp in the loop (validated R10/R13/R14).
__global__ void __launch_bounds__(32, 7)
lstm_ut(const float* __restrict__ x,        // [B, T, 1]
        const float* __restrict__ w_ih,     // [4H, 1]
        const float* __restrict__ w_hh,     // [4H, H]
        const float* __restrict__ b_ih,     // [4H]
        const float* __restrict__ b_hh,     // [4H]
        const float* __restrict__ w_dense,  // [1, H]
        const float* __restrict__ b_dense,  // [1]
        float* __restrict__ out)            // [B, T, 1]
{
    __shared__ __align__(16) float hsh[2][2][32];   // [ping][seq][slot]

    const int lane = (int)(threadIdx.x & 31u);
    const int j = (lane < HH) ? lane : (HH - 1);
    const int seqA = blockIdx.x * 2;

    // ---- per-lane weights: 4 gate rows (i,f,o prescaled 0.5; g by 1.0),
    //      plus the lane-uniform dense row. Bias in pair-12 hi slot. ----
    u64 W[4][13], Wd[13];
    float uu[4];
#pragma unroll
    for (int g = 0; g < 4; g++) {
        const float sc = (g == 2) ? 1.0f : 0.5f;
        const float* row = w_hh + (g * HH + j) * HH;
#pragma unroll
        for (int p = 0; p < 12; p++)
            W[g][p] = pk2(sc * row[2 * p], sc * row[2 * p + 1]);
        W[g][12] = pk2(sc * row[24], sc * (b_ih[g * HH + j] + b_hh[g * HH + j]));
        uu[g] = sc * w_ih[g * HH + j];
    }
#pragma unroll
    for (int p = 0; p < 12; p++)
        Wd[p] = pk2(w_dense[2 * p], w_dense[2 * p + 1]);
    Wd[12] = pk2(w_dense[24], b_dense[0]);

    const float2* xpA = reinterpret_cast<const float2*>(x + (size_t)seqA * TT);
    const float2* xpB = reinterpret_cast<const float2*>(x + (size_t)(seqA + 1) * TT);
    float* oA = out + (size_t)seqA * TT;
    float* oB = out + (size_t)(seqA + 1) * TT;

    const unsigned base = (unsigned)__cvta_generic_to_shared(&hsh[0][0][0]);
    const unsigned hA0 = base,        hB0 = base + 128u;   // ping 0
    const unsigned hA1 = base + 256u, hB1 = base + 384u;   // ping 1
    const unsigned shl = 4u * (unsigned)lane;

    // init: h = 0 everywhere, slot 25 = 1.0 (permanent bias feed)
    {
        const float v = (lane == HH) ? 1.0f : 0.0f;
        hsh[0][0][lane] = v; hsh[0][1][lane] = v;
        hsh[1][0][lane] = v; hsh[1][1][lane] = v;
    }
    __syncwarp();

    float cA = 0.0f, cB = 0.0f;
    float2 xqA = xpA[0], xqB = xpB[0];

    // One sequence's step. RA: read buf (holds h[t-1] pairs + const-1 slot);
    // WA: write buf; XV: x[t]; CC: c state; OP: out row; stores y[t-1].
#define SEQSTEP(RA, WA, XV, CC, OP, STORE0, GT)                               \
    {                                                                         \
        u64 p[13];                                                            \
        lds128((RA) +  0u, p[0], p[1]);                                       \
        lds128((RA) + 16u, p[2], p[3]);                                       \
        lds128((RA) + 32u, p[4], p[5]);                                       \
        lds128((RA) + 48u, p[6], p[7]);                                       \
        lds128((RA) + 64u, p[8], p[9]);                                       \
        lds128((RA) + 80u, p[10], p[11]);                                     \
        p[12] = lds64((RA) + 96u);                                            \
        /* split dots: low half pairs 0-6, high half pairs 7-12 */            \
        u64 L0 = fmul2(p[0], W[0][0]), L1 = fmul2(p[0], W[1][0]);             \
        u64 L2 = fmul2(p[0], W[2][0]), L3 = fmul2(p[0], W[3][0]);             \
        u64 LD = fmul2(p[0], Wd[0]);                                          \
        u64 H0 = fmul2(p[7], W[0][7]), H1 = fmul2(p[7], W[1][7]);             \
        u64 H2 = fmul2(p[7], W[2][7]), H3 = fmul2(p[7], W[3][7]);             \
        u64 HD = fmul2(p[7], Wd[7]);                                          \
        _Pragma("unroll")                                                     \
        for (int q = 1; q < 7; q++) {                                         \
            L0 = ffma2(p[q], W[0][q], L0);  L1 = ffma2(p[q], W[1][q], L1);    \
            L2 = ffma2(p[q], W[2][q], L2);  L3 = ffma2(p[q], W[3][q], L3);    \
            LD = ffma2(p[q], Wd[q], LD);                                      \
        }                                                                     \
        _Pragma("unroll")                                                     \
        for (int q = 8; q < 13; q++) {                                        \
            H0 = ffma2(p[q], W[0][q], H0);  H1 = ffma2(p[q], W[1][q], H1);    \
            H2 = ffma2(p[q], W[2][q], H2);  H3 = ffma2(p[q], W[3][q], H3);    \
            HD = ffma2(p[q], Wd[q], HD);                                      \
        }                                                                     \
        const u64 S0 = fadd2(L0, H0), S1 = fadd2(L1, H1);                     \
        const u64 S2 = fadd2(L2, H2), S3 = fadd2(L3, H3);                     \
        const u64 SD = fadd2(LD, HD);                                         \
        const float a0 = fmaf((XV), uu[0], lo2(S0) + hi2(S0));                \
        const float a1 = fmaf((XV), uu[1], lo2(S1) + hi2(S1));                \
        const float a2 = fmaf((XV), uu[2], lo2(S2) + hi2(S2));                \
        const float a3 = fmaf((XV), uu[3], lo2(S3) + hi2(S3));                \
        /* dense dot on h[t-1] == y[t-1]; lane-uniform, lane 0 stores */      \
        if ((STORE0) && lane == 0) (OP)[(GT) - 1] = lo2(SD) + hi2(SD);        \
        const float t0 = tanha(a0), t1 = tanha(a1);                           \
        const float t2 = tanha(a2), t3 = tanha(a3);                           \
        const float gi = fmaf(0.5f, t0, 0.5f);                                \
        const float gf = fmaf(0.5f, t1, 0.5f);                                \
        const float go = fmaf(0.5f, t3, 0.5f);                                \
        (CC) = fmaf(gf, (CC), gi * t2);                                       \
        const float hv = go * tanha(CC);                                      \
        if (lane < HH) sts32((WA) + shl, hv);                                 \
    }

#pragma unroll 1
    for (int tb = 0; tb < TT / 2; tb++) {
        const int tn = (tb + 1 < TT / 2) ? tb + 1 : tb;
        float2 xnA = xpA[tn], xnB = xpB[tn];
        // even step: read ping0, write ping1
        SEQSTEP(hA0, hA1, xqA.x, cA, oA, (tb > 0), 2 * tb)
        SEQSTEP(hB0, hB1, xqB.x, cB, oB, (tb > 0), 2 * tb)
        // odd step: read ping1, write ping0
        SEQSTEP(hA1, hA0, xqA.y, cA, oA, true, 2 * tb + 1)
        SEQSTEP(hB1, hB0, xqB.y, cB, oB, true, 2 * tb + 1)
        xqA = xnA; xqB = xnB;
    }
#undef SEQSTEP

    // tail: y[T-1] from final h (in ping 0), lane-uniform dense dot
    __syncwarp();
    {
        u64 dA = fmul2(lds64(hA0), Wd[0]);
        u64 dB = fmul2(lds64(hB0), Wd[0]);
#pragma unroll
        for (int p = 1; p < 13; p++) {
            dA = ffma2(lds64(hA0 + 8u * p), Wd[p], dA);
            dB = ffma2(lds64(hB0 + 8u * p), Wd[p], dB);
        }
        if (lane == 0) {
            oA[TT - 1] = lo2(dA) + hi2(dA);
            oB[TT - 1] = lo2(dB) + hi2(dB);
        }
    }
}

extern "C" void kernel_launch(void* const* d_in, const int* in_sizes, int n_in,
                              void* d_out, int out_size) {
    const float* x       = (const float*)d_in[0];
    const float* w_ih    = (const float*)d_in[1];
    const float* w_hh    = (const float*)d_in[2];
    const float* b_ih    = (const float*)d_in[3];
    const float* b_hh    = (const float*)d_in[4];
    const float* w_dense = (const float*)d_in[5];
    const float* b_dense = (const float*)d_in[6];
    float* out = (float*)d_out;

    // 1024 CTAs x 32 threads: one warp per CTA, two sequences per warp,
    // unit-owned state, one smem round-trip per step.
    lstm_ut<<<BATCH / 2, 32>>>(x, w_ih, w_hh, b_ih, b_hh,
                               w_dense, b_dense, out);
}

// round 16
// speedup vs baseline: 1.3079x; 1.3079x over previous
#include <cuda_runtime.h>

#define BATCH 2048
#define TT    2048
#define HH    25

typedef unsigned long long u64;

// Packed f32x2 ops (Blackwell, PTX-only): two fp32 ops per instruction.
__device__ __forceinline__ u64 ffma2(u64 a, u64 b, u64 c) {
    u64 d; asm("fma.rn.f32x2 %0, %1, %2, %3;" : "=l"(d) : "l"(a), "l"(b), "l"(c)); return d;
}
__device__ __forceinline__ u64 fmul2(u64 a, u64 b) {
    u64 d; asm("mul.rn.f32x2 %0, %1, %2;" : "=l"(d) : "l"(a), "l"(b)); return d;
}
__device__ __forceinline__ u64 fadd2(u64 a, u64 b) {
    u64 d; asm("add.rn.f32x2 %0, %1, %2;" : "=l"(d) : "l"(a), "l"(b)); return d;
}
__device__ __forceinline__ u64 pk2(float lo, float hi) {
    u64 r; asm("mov.b64 %0, {%1, %2};" : "=l"(r) : "f"(lo), "f"(hi)); return r;
}
__device__ __forceinline__ float lo2(u64 a) { return __uint_as_float((unsigned)a); }
__device__ __forceinline__ float hi2(u64 a) { return __uint_as_float((unsigned)(a >> 32)); }

// MUFU.TANH: single-instruction tanh.
__device__ __forceinline__ float tanha(float x) {
    float r; asm("tanh.approx.f32 %0, %1;" : "=f"(r) : "f"(x)); return r;
}

__device__ __forceinline__ u64 lds64(unsigned a) {
    u64 r; asm volatile("ld.shared.b64 %0, [%1];" : "=l"(r) : "r"(a) : "memory"); return r;
}
__device__ __forceinline__ void lds128(unsigned a, u64& p0, u64& p1) {
    asm volatile("ld.shared.v2.u64 {%0, %1}, [%2];" : "=l"(p0), "=l"(p1) : "r"(a) : "memory");
}
__device__ __forceinline__ void sts32(unsigned a, float v) {
    asm volatile("st.shared.f32 [%0], %1;" :: "r"(a), "f"(v) : "memory");
}

// Unit-owned dual-sequence LSTM, MUFU.TANH, split dot chains, dense head in
// lane 25 -- R14's FMA op count with R15's short serial chain.
// Lane j<25 owns unit j of both sequences: slots 0..3 = gate rows i,f,g,o
// (i,f,o prescaled by 0.5 for sigmoid(z)=0.5+0.5*tanh(z/2); g by 1.0), so all
// 4 gates, c_j, h_j are lane-local -> NO gate smem round-trip. Lane 25's
// slot 0 holds the UNSCALED dense row (uu=0, bias in pair-12 hi slot vs the
// const-1.0 kept in h slot 25): its raw dot over h[t-1] IS y[t-1], stored by
// lane 25 directly. Lanes 26..31 carry zero weights (inert). 4 packed dots
// per lane (same FMA work as R14), each split into halves (pairs 0-6 / 7-12)
// merged with one packed add -> dot latency ~36 vs 52. Per seq-step MIO:
// 6 LDS.128 + 1 LDS.64 + 1 STS.32 (vs 17 in R14). Warp-private smem,
// in-order per-warp LSU -> no syncwarp in the loop (validated R10/R13/R14).
__global__ void __launch_bounds__(32, 7)
lstm_u25(const float* __restrict__ x,        // [B, T, 1]
         const float* __restrict__ w_ih,     // [4H, 1]
         const float* __restrict__ w_hh,     // [4H, H]
         const float* __restrict__ b_ih,     // [4H]
         const float* __restrict__ b_hh,     // [4H]
         const float* __restrict__ w_dense,  // [1, H]
         const float* __restrict__ b_dense,  // [1]
         float* __restrict__ out)            // [B, T, 1]
{
    __shared__ __align__(16) float hsh[2][2][32];   // [ping][seq][slot]

    const int lane = (int)(threadIdx.x & 31u);
    const int seqA = blockIdx.x * 2;

    // ---- per-lane weights: slots 0..3 ----
    u64 W[4][13];
    float uu[4];
    if (lane < HH) {
        const int j = lane;
#pragma unroll
        for (int g = 0; g < 4; g++) {
            const float sc = (g == 2) ? 1.0f : 0.5f;
            const float* row = w_hh + (g * HH + j) * HH;
#pragma unroll
            for (int p = 0; p < 12; p++)
                W[g][p] = pk2(sc * row[2 * p], sc * row[2 * p + 1]);
            W[g][12] = pk2(sc * row[24],
                           sc * (b_ih[g * HH + j] + b_hh[g * HH + j]));
            uu[g] = sc * w_ih[g * HH + j];
        }
    } else if (lane == HH) {      // lane 25: slot 0 = dense row (unscaled)
#pragma unroll
        for (int p = 0; p < 12; p++)
            W[0][p] = pk2(w_dense[2 * p], w_dense[2 * p + 1]);
        W[0][12] = pk2(w_dense[24], b_dense[0]);
#pragma unroll
        for (int g = 1; g < 4; g++)
#pragma unroll
            for (int p = 0; p < 13; p++) W[g][p] = 0ull;
        uu[0] = uu[1] = uu[2] = uu[3] = 0.0f;
    } else {                      // lanes 26..31: inert
#pragma unroll
        for (int g = 0; g < 4; g++)
#pragma unroll
            for (int p = 0; p < 13; p++) W[g][p] = 0ull;
        uu[0] = uu[1] = uu[2] = uu[3] = 0.0f;
    }

    const float2* xpA = reinterpret_cast<const float2*>(x + (size_t)seqA * TT);
    const float2* xpB = reinterpret_cast<const float2*>(x + (size_t)(seqA + 1) * TT);
    float* oA = out + (size_t)seqA * TT;
    float* oB = out + (size_t)(seqA + 1) * TT;

    const unsigned base = (unsigned)__cvta_generic_to_shared(&hsh[0][0][0]);
    const unsigned hA0 = base,        hB0 = base + 128u;   // ping 0
    const unsigned hA1 = base + 256u, hB1 = base + 384u;   // ping 1
    const unsigned shl = 4u * (unsigned)lane;

    // init: h = 0, slot 25 = 1.0 (permanent bias feed; lane 25 never stores)
    {
        const float v = (lane == HH) ? 1.0f : 0.0f;
        hsh[0][0][lane] = v; hsh[0][1][lane] = v;
        hsh[1][0][lane] = v; hsh[1][1][lane] = v;
    }
    __syncwarp();

    float cA = 0.0f, cB = 0.0f;
    float2 xqA = xpA[0], xqB = xpB[0];

    // One step, both sequences interleaved (16 independent half-chains).
#define STEP(RAA, RAB, WAA, WAB, XA, XB, STORE0, GT)                          \
    {                                                                         \
        u64 pa[13], pb[13];                                                   \
        lds128((RAA) +  0u, pa[0], pa[1]);  lds128((RAB) +  0u, pb[0], pb[1]);\
        lds128((RAA) + 16u, pa[2], pa[3]);  lds128((RAB) + 16u, pb[2], pb[3]);\
        lds128((RAA) + 32u, pa[4], pa[5]);  lds128((RAB) + 32u, pb[4], pb[5]);\
        lds128((RAA) + 48u, pa[6], pa[7]);  lds128((RAB) + 48u, pb[6], pb[7]);\
        lds128((RAA) + 64u, pa[8], pa[9]);  lds128((RAB) + 64u, pb[8], pb[9]);\
        lds128((RAA) + 80u, pa[10], pa[11]);lds128((RAB) + 80u, pb[10], pb[11]);\
        pa[12] = lds64((RAA) + 96u);        pb[12] = lds64((RAB) + 96u);      \
        u64 LA0 = fmul2(pa[0], W[0][0]), LA1 = fmul2(pa[0], W[1][0]);         \
        u64 LA2 = fmul2(pa[0], W[2][0]), LA3 = fmul2(pa[0], W[3][0]);         \
        u64 HA0 = fmul2(pa[7], W[0][7]), HA1 = fmul2(pa[7], W[1][7]);         \
        u64 HA2 = fmul2(pa[7], W[2][7]), HA3 = fmul2(pa[7], W[3][7]);         \
        u64 LB0 = fmul2(pb[0], W[0][0]), LB1 = fmul2(pb[0], W[1][0]);         \
        u64 LB2 = fmul2(pb[0], W[2][0]), LB3 = fmul2(pb[0], W[3][0]);         \
        u64 HB0 = fmul2(pb[7], W[0][7]), HB1 = fmul2(pb[7], W[1][7]);         \
        u64 HB2 = fmul2(pb[7], W[2][7]), HB3 = fmul2(pb[7], W[3][7]);         \
        _Pragma("unroll")                                                     \
        for (int q = 1; q < 7; q++) {                                         \
            LA0 = ffma2(pa[q], W[0][q], LA0); LB0 = ffma2(pb[q], W[0][q], LB0);\
            LA1 = ffma2(pa[q], W[1][q], LA1); LB1 = ffma2(pb[q], W[1][q], LB1);\
            LA2 = ffma2(pa[q], W[2][q], LA2); LB2 = ffma2(pb[q], W[2][q], LB2);\
            LA3 = ffma2(pa[q], W[3][q], LA3); LB3 = ffma2(pb[q], W[3][q], LB3);\
        }                                                                     \
        _Pragma("unroll")                                                     \
        for (int q = 8; q < 13; q++) {                                        \
            HA0 = ffma2(pa[q], W[0][q], HA0); HB0 = ffma2(pb[q], W[0][q], HB0);\
            HA1 = ffma2(pa[q], W[1][q], HA1); HB1 = ffma2(pb[q], W[1][q], HB1);\
            HA2 = ffma2(pa[q], W[2][q], HA2); HB2 = ffma2(pb[q], W[2][q], HB2);\
            HA3 = ffma2(pa[q], W[3][q], HA3); HB3 = ffma2(pb[q], W[3][q], HB3);\
        }                                                                     \
        const u64 SA0 = fadd2(LA0, HA0), SA1 = fadd2(LA1, HA1);               \
        const u64 SA2 = fadd2(LA2, HA2), SA3 = fadd2(LA3, HA3);               \
        const u64 SB0 = fadd2(LB0, HB0), SB1 = fadd2(LB1, HB1);               \
        const u64 SB2 = fadd2(LB2, HB2), SB3 = fadd2(LB3, HB3);               \
        const float aA0 = fmaf((XA), uu[0], lo2(SA0) + hi2(SA0));             \
        const float aA1 = fmaf((XA), uu[1], lo2(SA1) + hi2(SA1));             \
        const float aA2 = fmaf((XA), uu[2], lo2(SA2) + hi2(SA2));             \
        const float aA3 = fmaf((XA), uu[3], lo2(SA3) + hi2(SA3));             \
        const float aB0 = fmaf((XB), uu[0], lo2(SB0) + hi2(SB0));             \
        const float aB1 = fmaf((XB), uu[1], lo2(SB1) + hi2(SB1));             \
        const float aB2 = fmaf((XB), uu[2], lo2(SB2) + hi2(SB2));             \
        const float aB3 = fmaf((XB), uu[3], lo2(SB3) + hi2(SB3));             \
        /* lane 25 slot 0: raw dense dot on h[t-1] == y[t-1] (uu=0) */        \
        if ((STORE0) && lane == HH) {                                         \
            oA[(GT) - 1] = aA0;  oB[(GT) - 1] = aB0;                          \
        }                                                                     \
        const float tA0 = tanha(aA0), tA1 = tanha(aA1);                       \
        const float tA2 = tanha(aA2), tA3 = tanha(aA3);                       \
        const float tB0 = tanha(aB0), tB1 = tanha(aB1);                       \
        const float tB2 = tanha(aB2), tB3 = tanha(aB3);                       \
        const float giA = fmaf(0.5f, tA0, 0.5f), gfA = fmaf(0.5f, tA1, 0.5f); \
        const float goA = fmaf(0.5f, tA3, 0.5f);                              \
        const float giB = fmaf(0.5f, tB0, 0.5f), gfB = fmaf(0.5f, tB1, 0.5f); \
        const float goB = fmaf(0.5f, tB3, 0.5f);                              \
        cA = fmaf(gfA, cA, giA * tA2);                                        \
        cB = fmaf(gfB, cB, giB * tB2);                                        \
        const float hvA = goA * tanha(cA);                                    \
        const float hvB = goB * tanha(cB);                                    \
        if (lane < HH) { sts32((WAA) + shl, hvA); sts32((WAB) + shl, hvB); }  \
    }

#pragma unroll 1
    for (int tb = 0; tb < TT / 2; tb++) {
        const int tn = (tb + 1 < TT / 2) ? tb + 1 : tb;
        float2 xnA = xpA[tn], xnB = xpB[tn];
        STEP(hA0, hB0, hA1, hB1, xqA.x, xqB.x, (tb > 0), 2 * tb)
        STEP(hA1, hB1, hA0, hB0, xqA.y, xqB.y, true,     2 * tb + 1)
        xqA = xnA; xqB = xnB;
    }
#undef STEP

    // tail: y[T-1] from final h (ping 0) via lane 25's dense chain (slot 0)
    __syncwarp();
    {
        u64 dA = fmul2(lds64(hA0), W[0][0]);
        u64 dB = fmul2(lds64(hB0), W[0][0]);
#pragma unroll
        for (int p = 1; p < 13; p++) {
            dA = ffma2(lds64(hA0 + 8u * p), W[0][p], dA);
            dB = ffma2(lds64(hB0 + 8u * p), W[0][p], dB);
        }
        if (lane == HH) {
            oA[TT - 1] = lo2(dA) + hi2(dA);
            oB[TT - 1] = lo2(dB) + hi2(dB);
        }
    }
}

extern "C" void kernel_launch(void* const* d_in, const int* in_sizes, int n_in,
                              void* d_out, int out_size) {
    const float* x       = (const float*)d_in[0];
    const float* w_ih    = (const float*)d_in[1];
    const float* w_hh    = (const float*)d_in[2];
    const float* b_ih    = (const float*)d_in[3];
    const float* b_hh    = (const float*)d_in[4];
    const float* w_dense = (const float*)d_in[5];
    const float* b_dense = (const float*)d_in[6];
    float* out = (float*)d_out;

    // 1024 CTAs x 32 threads: one warp per CTA, two sequences per warp,
    // unit-owned gates + lane-25 dense head, one STS per seq-step.
    lstm_u25<<<BATCH / 2, 32>>>(x, w_ih, w_hh, b_ih, b_hh,
                                w_dense, b_dense, out);
}